// round 12
// baseline (speedup 1.0000x reference)
#include <cuda_runtime.h>
#include <cstdint>

#define Bdim 4
#define Tdim 256
#define Sdim 256
#define Ddim 512

// Scratch (allocation-free rule: __device__ globals)
__device__ float g_wq[Bdim * Tdim * Ddim];    // 2 MB
__device__ float g_uh[Bdim * Sdim * Ddim];    // 2 MB
__device__ float g_sc[Bdim * Tdim * Sdim];    // 1 MB attn
__device__ float g_pre1[Bdim * Sdim * Ddim];  // 2 MB  ctx @ Wout_top
__device__ float g_pre2[Bdim * Tdim * Ddim];  // 2 MB  output @ Wout_bot + bout

__device__ __forceinline__ float tanh_fast(float x) {
    float y;
    asm("tanh.approx.f32 %0, %1;" : "=f"(y) : "f"(x));
    return y;
}

__device__ __forceinline__ uint32_t raw_tf32(float x) {
    return __float_as_uint(x);
}

// ---- packed f32x2 helpers (Blackwell) ----
__device__ __forceinline__ uint64_t pack2(float lo, float hi) {
    uint64_t r;
    asm("mov.b64 %0, {%1, %2};" : "=l"(r) : "f"(lo), "f"(hi));
    return r;
}
__device__ __forceinline__ void unpack2(float& lo, float& hi, uint64_t v) {
    asm("mov.b64 {%0, %1}, %2;" : "=f"(lo), "=f"(hi) : "l"(v));
}
__device__ __forceinline__ uint64_t fadd2(uint64_t a, uint64_t b) {
    uint64_t d;
    asm("add.rn.f32x2 %0, %1, %2;" : "=l"(d) : "l"(a), "l"(b));
    return d;
}
__device__ __forceinline__ uint64_t ffma2(uint64_t a, uint64_t b, uint64_t c) {
    uint64_t d;
    asm("fma.rn.f32x2 %0, %1, %2, %3;" : "=l"(d) : "l"(a), "l"(b), "l"(c));
    return d;
}

__device__ __forceinline__ void mma_tf32(float* d, const uint32_t* a,
                                         const uint32_t* b) {
    asm volatile(
        "mma.sync.aligned.m16n8k8.row.col.f32.tf32.tf32.f32 "
        "{%0,%1,%2,%3}, {%4,%5,%6,%7}, {%8,%9}, {%0,%1,%2,%3};"
        : "+f"(d[0]), "+f"(d[1]), "+f"(d[2]), "+f"(d[3])
        : "r"(a[0]), "r"(a[1]), "r"(a[2]), "r"(a[3]), "r"(b[0]), "r"(b[1]));
}

#define CP16(dst, src) \
    asm volatile("cp.async.cg.shared.global [%0], [%1], 16;" \
                 :: "r"(dst), "l"(src) : "memory")
#define CP_COMMIT() asm volatile("cp.async.commit_group;" ::: "memory")
#define CP_WAIT2()  asm volatile("cp.async.wait_group 2;" ::: "memory")
#define CP_WAIT1()  asm volatile("cp.async.wait_group 1;" ::: "memory")

#define LDA 20
#define LDB 72

// ---------------------------------------------------------------------------
// gemm4: four independent 1024x512x512 jobs. 256 threads, CTA tile 128x64,
// 8 warps (4m x 2n), warp tile 32x32, BK=16, 3-stage cp.async, raw tf32.
// ---------------------------------------------------------------------------
#define G4STG 3
#define G4_AB (128 * LDA * 4)
#define G4_BB (16 * LDB * 4)

struct Job {
    const float* A;
    const float* B;
    const float* bias;
    float* C;
};

__global__ __launch_bounds__(256) void gemm4(Job j0, Job j1, Job j2, Job j3)
{
    __shared__ float As[G4STG][128 * LDA];
    __shared__ float Bs[G4STG][16 * LDB];

    Job j = (blockIdx.z == 0) ? j0 : (blockIdx.z == 1) ? j1
          : (blockIdx.z == 2) ? j2 : j3;

    const int tid = threadIdx.x;
    const int wid = tid >> 5;
    const int lane = tid & 31;
    const int g = lane >> 2;
    const int tig = lane & 3;
    const int warp_m = wid >> 1;
    const int warp_n = wid & 1;

    const int m0 = blockIdx.y * 128;
    const int n0 = blockIdx.x * 64;

    const int ar = tid >> 1;
    const int ak = (tid & 1) << 3;
    const int br = tid >> 4;
    const int bc = (tid & 15) << 2;

    uint32_t as_s = (uint32_t)__cvta_generic_to_shared(&As[0][0]);
    uint32_t bs_s = (uint32_t)__cvta_generic_to_shared(&Bs[0][0]);

    const int NT = Ddim >> 4;  // 32

    float acc[2][4][4];
#pragma unroll
    for (int i = 0; i < 2; i++)
#pragma unroll
        for (int jj = 0; jj < 4; jj++)
#pragma unroll
            for (int q = 0; q < 4; q++) acc[i][jj][q] = 0.f;

    auto issue = [&](int stage, int kt) {
        const int kg = kt << 4;
        const float* s0 = j.A + (long)(m0 + ar) * Ddim + kg + ak;
        uint32_t d0 = as_s + stage * G4_AB + (ar * LDA + ak) * 4;
        CP16(d0, s0);
        CP16(d0 + 16, s0 + 4);
        const float* sb = j.B + (long)(kg + br) * Ddim + n0 + bc;
        uint32_t db = bs_s + stage * G4_BB + (br * LDB + bc) * 4;
        CP16(db, sb);
    };

    issue(0, 0); CP_COMMIT();
    issue(1, 1); CP_COMMIT();

    for (int t = 0; t < NT; t++) {
        const int st = t % G4STG;
        CP_WAIT1();
        __syncthreads();

        if (t + 2 < NT) issue((t + 2) % G4STG, t + 2);
        CP_COMMIT();

        const float* as = As[st];
        const float* bs = Bs[st];
        const int mb = warp_m * 32;
        const int nb = warp_n * 32;
#pragma unroll
        for (int ks = 0; ks < 2; ks++) {
            const int k0 = ks << 3;
            uint32_t a[2][4], b[4][2];
#pragma unroll
            for (int im = 0; im < 2; im++) {
                const float* ap = as + (mb + im * 16 + g) * LDA;
                a[im][0] = raw_tf32(ap[k0 + tig]);
                a[im][1] = raw_tf32(ap[8 * LDA + k0 + tig]);
                a[im][2] = raw_tf32(ap[k0 + tig + 4]);
                a[im][3] = raw_tf32(ap[8 * LDA + k0 + tig + 4]);
            }
#pragma unroll
            for (int in = 0; in < 4; in++) {
                const int nc = nb + in * 8 + g;
                b[in][0] = raw_tf32(bs[(k0 + tig) * LDB + nc]);
                b[in][1] = raw_tf32(bs[(k0 + tig + 4) * LDB + nc]);
            }
#pragma unroll
            for (int im = 0; im < 2; im++)
#pragma unroll
                for (int in = 0; in < 4; in++)
                    mma_tf32(acc[im][in], a[im], b[in]);
        }
    }

    __syncthreads();
    const int mb = warp_m * 32;
    const int nb = warp_n * 32;
#pragma unroll
    for (int im = 0; im < 2; im++) {
#pragma unroll
        for (int in = 0; in < 4; in++) {
            const int row = m0 + mb + im * 16 + g;
            const int col = n0 + nb + in * 8 + tig * 2;
            float bx = 0.f, by = 0.f;
            if (j.bias) { bx = j.bias[col]; by = j.bias[col + 1]; }
            float2 o0 = make_float2(acc[im][in][0] + bx, acc[im][in][1] + by);
            float2 o1 = make_float2(acc[im][in][2] + bx, acc[im][in][3] + by);
            *(float2*)&j.C[(long)row * Ddim + col] = o0;
            *(float2*)&j.C[(long)(row + 8) * Ddim + col] = o1;
        }
    }
}

// ---------------------------------------------------------------------------
// gemm_fin: out[b] = attn[b] @ pre1[b] + pre2[b]  (256x512, K=256 per batch)
// ---------------------------------------------------------------------------
#define FSTG 4
#define F_AB (64 * LDA * 4)
#define F_BB (16 * LDB * 4)

__global__ __launch_bounds__(256) void gemm_fin(
    const float* __restrict__ attn, const float* __restrict__ pre1,
    const float* __restrict__ pre2, float* __restrict__ out)
{
    __shared__ float As[FSTG][64 * LDA];
    __shared__ float Bs[FSTG][16 * LDB];

    const int z = blockIdx.z;
    const float* A = attn + (long)z * Tdim * Sdim;
    const float* B = pre1 + (long)z * Sdim * Ddim;
    const float* addend = pre2 + (long)z * Tdim * Ddim;
    float* C = out + (long)z * Tdim * Ddim;

    const int tid = threadIdx.x;
    const int wid = tid >> 5;
    const int lane = tid & 31;
    const int g = lane >> 2;
    const int tig = lane & 3;
    const int warp_m = wid >> 2;
    const int warp_n = wid & 3;

    const int m0 = blockIdx.y * 64;
    const int n0 = blockIdx.x * 64;

    const int ar = tid >> 2;
    const int ak = (tid & 3) << 2;
    const int br = tid >> 4;
    const int bc = (tid & 15) << 2;

    uint32_t as_s = (uint32_t)__cvta_generic_to_shared(&As[0][0]);
    uint32_t bs_s = (uint32_t)__cvta_generic_to_shared(&Bs[0][0]);

    const int NT = Sdim >> 4;  // 16

    float acc[2][2][4];
#pragma unroll
    for (int i = 0; i < 2; i++)
#pragma unroll
        for (int jj = 0; jj < 2; jj++)
#pragma unroll
            for (int q = 0; q < 4; q++) acc[i][jj][q] = 0.f;

    auto issue = [&](int stage, int kt) {
        const int kg = kt << 4;
        const float* s0 = A + (long)(m0 + ar) * Sdim + kg + ak;
        uint32_t d0 = as_s + stage * F_AB + (ar * LDA + ak) * 4;
        CP16(d0, s0);
        const float* sb = B + (long)(kg + br) * Ddim + n0 + bc;
        uint32_t db = bs_s + stage * F_BB + (br * LDB + bc) * 4;
        CP16(db, sb);
    };

#pragma unroll
    for (int p = 0; p < FSTG - 1; p++) {
        if (p < NT) issue(p, p);
        CP_COMMIT();
    }

    for (int t = 0; t < NT; t++) {
        const int st = t & (FSTG - 1);
        CP_WAIT2();
        __syncthreads();

        if (t + FSTG - 1 < NT) issue((t + FSTG - 1) & (FSTG - 1), t + FSTG - 1);
        CP_COMMIT();

        const float* as = As[st];
        const float* bs = Bs[st];
        const int mb = warp_m * 32;
        const int nb = warp_n * 16;
#pragma unroll
        for (int ks = 0; ks < 2; ks++) {
            const int k0 = ks << 3;
            uint32_t a[2][4], b[2][2];
#pragma unroll
            for (int im = 0; im < 2; im++) {
                const float* ap = as + (mb + im * 16 + g) * LDA;
                a[im][0] = raw_tf32(ap[k0 + tig]);
                a[im][1] = raw_tf32(ap[8 * LDA + k0 + tig]);
                a[im][2] = raw_tf32(ap[k0 + tig + 4]);
                a[im][3] = raw_tf32(ap[8 * LDA + k0 + tig + 4]);
            }
#pragma unroll
            for (int in = 0; in < 2; in++) {
                const int nc = nb + in * 8 + g;
                b[in][0] = raw_tf32(bs[(k0 + tig) * LDB + nc]);
                b[in][1] = raw_tf32(bs[(k0 + tig + 4) * LDB + nc]);
            }
#pragma unroll
            for (int im = 0; im < 2; im++)
#pragma unroll
                for (int in = 0; in < 2; in++)
                    mma_tf32(acc[im][in], a[im], b[in]);
        }
    }

    __syncthreads();
    const int mb = warp_m * 32;
    const int nb = warp_n * 16;
#pragma unroll
    for (int im = 0; im < 2; im++) {
#pragma unroll
        for (int in = 0; in < 2; in++) {
            const int row = m0 + mb + im * 16 + g;
            const int col = n0 + nb + in * 8 + tig * 2;
            const float2 r0 = *(const float2*)&addend[(long)row * Ddim + col];
            const float2 r1 = *(const float2*)&addend[(long)(row + 8) * Ddim + col];
            float2 o0 = make_float2(acc[im][in][0] + r0.x, acc[im][in][1] + r0.y);
            float2 o1 = make_float2(acc[im][in][2] + r1.x, acc[im][in][3] + r1.y);
            *(float2*)&C[(long)row * Ddim + col] = o0;
            *(float2*)&C[(long)(row + 8) * Ddim + col] = o1;
        }
    }
}

// ---------------------------------------------------------------------------
// Fused score + masked softmax.
// Grid (Tdim/8, Bdim), 256 threads. Warp w owns t-row t0+w.
// Lane covers s = {64p + 2*lane, 64p + 2*lane + 1 : p=0..3} (4 packed pairs).
// Inner math in packed f32x2 (1 fma-pipe op per 2 tanh).
// Softmax: max over ALL 256 s, exp, keep-mask, renormalize (reference).
// ---------------------------------------------------------------------------
__global__ __launch_bounds__(256) void score_sm_kernel(
    const float* __restrict__ wq, const float* __restrict__ uh,
    const float* __restrict__ v, const int* __restrict__ mask,
    float* __restrict__ attn, float* __restrict__ attn_out)
{
    __shared__ float uhs[32][256];   // [d][s] chunk, 32 KB
    __shared__ float wqs[8][32];     // [t][d] chunk
    __shared__ float vsm[32];
    __shared__ float keeps[256];

    const int b = blockIdx.y;
    const int t0 = blockIdx.x * 8;
    const int tid = threadIdx.x;
    const int wid = tid >> 5;
    const int lane = tid & 31;

    const float* uhb = uh + (long)b * Sdim * Ddim;
    const float* wqb = wq + ((long)b * Tdim + t0) * Ddim;

    keeps[tid] = 1.0f - (float)mask[b * Sdim + tid];

    uint64_t acc2[4];
#pragma unroll
    for (int p = 0; p < 4; p++) acc2[p] = pack2(0.f, 0.f);

    for (int d0 = 0; d0 < Ddim; d0 += 32) {
        // load uh chunk transposed: thread = s-row, 8 x float4 over d
        {
            const float* up = uhb + (long)tid * Ddim + d0;
#pragma unroll
            for (int k = 0; k < 8; k++) {
                float4 vv = *(const float4*)(up + k * 4);
                uhs[k * 4 + 0][tid] = vv.x;
                uhs[k * 4 + 1][tid] = vv.y;
                uhs[k * 4 + 2][tid] = vv.z;
                uhs[k * 4 + 3][tid] = vv.w;
            }
        }
        // wq chunk: 8 rows x 32 d
        wqs[tid >> 5][tid & 31] = wqb[(long)(tid >> 5) * Ddim + d0 + (tid & 31)];
        if (tid < 32) vsm[tid] = v[d0 + tid];
        __syncthreads();

#pragma unroll
        for (int dk = 0; dk < 32; dk++) {
            const float wv = wqs[wid][dk];
            const float vv = vsm[dk];
            const uint64_t wv2 = pack2(wv, wv);
            const uint64_t vv2 = pack2(vv, vv);
#pragma unroll
            for (int p = 0; p < 4; p++) {
                const uint64_t u2 =
                    *(const uint64_t*)&uhs[dk][p * 64 + 2 * lane];
                const uint64_t t2 = fadd2(u2, wv2);
                float lo, hi;
                unpack2(lo, hi, t2);
                const uint64_t th2 = pack2(tanh_fast(lo), tanh_fast(hi));
                acc2[p] = ffma2(th2, vv2, acc2[p]);
            }
        }
        __syncthreads();
    }

    // ---- softmax (reference semantics) ----
    float x[8];
#pragma unroll
    for (int p = 0; p < 4; p++) unpack2(x[2 * p], x[2 * p + 1], acc2[p]);

    float m = -1e30f;
#pragma unroll
    for (int i = 0; i < 8; i++) m = fmaxf(m, x[i]);
#pragma unroll
    for (int o = 16; o > 0; o >>= 1)
        m = fmaxf(m, __shfl_xor_sync(0xffffffffu, m, o));

    float e[8];
    float sum = 0.f;
#pragma unroll
    for (int p = 0; p < 4; p++) {
        const float2 kp = *(const float2*)&keeps[p * 64 + 2 * lane];
        e[2 * p + 0] = __expf(x[2 * p + 0] - m) * kp.x;
        e[2 * p + 1] = __expf(x[2 * p + 1] - m) * kp.y;
        sum += e[2 * p + 0] + e[2 * p + 1];
    }
#pragma unroll
    for (int o = 16; o > 0; o >>= 1)
        sum += __shfl_xor_sync(0xffffffffu, sum, o);

    const float inv = 1.0f / sum;
    const int row = b * Tdim + t0 + wid;
    float* rp = attn + (long)row * Sdim;
    float* ap = attn_out ? attn_out + (long)row * Sdim : nullptr;
#pragma unroll
    for (int p = 0; p < 4; p++) {
        float2 o = make_float2(e[2 * p] * inv, e[2 * p + 1] * inv);
        *(float2*)&rp[p * 64 + 2 * lane] = o;
        if (ap) *(float2*)&ap[p * 64 + 2 * lane] = o;
    }
}

// ---------------------------------------------------------------------------
extern "C" void kernel_launch(void* const* d_in, const int* in_sizes, int n_in,
                              void* d_out, int out_size)
{
    const float* out_in = (const float*)d_in[0];  // (B,T,D)
    const float* ctx    = (const float*)d_in[1];  // (B,S,D)
    const int*   mask   = (const int*)d_in[2];    // (B,S)
    const float* Wq     = (const float*)d_in[3];  // (D,D)
    const float* bq     = (const float*)d_in[4];  // (D,)
    const float* Wc     = (const float*)d_in[5];  // (D,D)
    const float* v      = (const float*)d_in[6];  // (D,)
    const float* Wout   = (const float*)d_in[7];  // (2D,D)
    const float* bout   = (const float*)d_in[8];  // (D,)

    float *p_wq, *p_uh, *p_sc, *p_pre1, *p_pre2;
    cudaGetSymbolAddress((void**)&p_wq, g_wq);
    cudaGetSymbolAddress((void**)&p_uh, g_uh);
    cudaGetSymbolAddress((void**)&p_sc, g_sc);
    cudaGetSymbolAddress((void**)&p_pre1, g_pre1);
    cudaGetSymbolAddress((void**)&p_pre2, g_pre2);

    const long BTD = (long)Bdim * Tdim * Ddim;  // 524288
    const long BTS = (long)Bdim * Tdim * Sdim;  // 262144
    float* out_f = (float*)d_out;
    float* attn_out = ((long)out_size >= BTD + BTS) ? (out_f + BTD) : nullptr;

    // 1) Four fused 1024x512x512 GEMMs
    Job j0{out_in, Wq, bq, p_wq};
    Job j1{ctx, Wc, nullptr, p_uh};
    Job j2{ctx, Wout, nullptr, p_pre1};
    Job j3{out_in, Wout + (long)Ddim * Ddim, bout, p_pre2};
    gemm4<<<dim3(Ddim / 64, (Bdim * Tdim) / 128, 4), 256>>>(j0, j1, j2, j3);

    // 2) fused score + masked softmax (attn to g_sc and d_out)
    score_sm_kernel<<<dim3(Tdim / 8, Bdim), 256>>>(
        p_wq, p_uh, v, mask, p_sc, attn_out);

    // 3) out = attn @ pre1 + pre2   (batched 256x512, K=256)
    gemm_fin<<<dim3(Ddim / 64, Tdim / 64, Bdim), 256>>>(p_sc, p_pre1, p_pre2, out_f);
}

// round 13
// speedup vs baseline: 1.2615x; 1.2615x over previous
#include <cuda_runtime.h>
#include <cstdint>

#define Bdim 4
#define Tdim 256
#define Sdim 256
#define Ddim 512

// Scratch (allocation-free rule: __device__ globals)
__device__ float g_wq[Bdim * Tdim * Ddim];    // 2 MB
__device__ float g_uh[Bdim * Sdim * Ddim];    // 2 MB
__device__ float g_sc[Bdim * Tdim * Sdim];    // 1 MB (scores, then attn)
__device__ float g_pre1[Bdim * Sdim * Ddim];  // 2 MB  ctx @ Wout_top
__device__ float g_pre2[Bdim * Tdim * Ddim];  // 2 MB  output @ Wout_bot + bout

__device__ __forceinline__ float tanh_fast(float x) {
    float y;
    asm("tanh.approx.f32 %0, %1;" : "=f"(y) : "f"(x));
    return y;
}

// Raw fp32 bits as tf32 operand (truncation) — saves cvt issue slots.
__device__ __forceinline__ uint32_t raw_tf32(float x) {
    return __float_as_uint(x);
}

__device__ __forceinline__ void mma_tf32(float* d, const uint32_t* a,
                                         const uint32_t* b) {
    asm volatile(
        "mma.sync.aligned.m16n8k8.row.col.f32.tf32.tf32.f32 "
        "{%0,%1,%2,%3}, {%4,%5,%6,%7}, {%8,%9}, {%0,%1,%2,%3};"
        : "+f"(d[0]), "+f"(d[1]), "+f"(d[2]), "+f"(d[3])
        : "r"(a[0]), "r"(a[1]), "r"(a[2]), "r"(a[3]), "r"(b[0]), "r"(b[1]));
}

#define CP16(dst, src) \
    asm volatile("cp.async.cg.shared.global [%0], [%1], 16;" \
                 :: "r"(dst), "l"(src) : "memory")
#define CP_COMMIT() asm volatile("cp.async.commit_group;" ::: "memory")
#define CP_WAIT2()  asm volatile("cp.async.wait_group 2;" ::: "memory")

#define LDA 20
#define LDB 72

// ---------------------------------------------------------------------------
// gemm4: four independent 1024x512x512 jobs. 256 threads, CTA tile 128x64,
// 8 warps (4m x 2n), warp tile 32x32, BK=16, 4-stage cp.async (dynamic smem),
// wait_group 2 -> ~3 iterations of latency tolerance.
// ---------------------------------------------------------------------------
#define G4STG 4
#define G4_AW (128 * LDA)          // floats per A stage
#define G4_BW (16 * LDB)           // floats per B stage
#define G4_AB (G4_AW * 4)
#define G4_BB (G4_BW * 4)
#define G4_DYN ((G4_AW + G4_BW) * G4STG * 4)   // 59392 bytes

struct Job {
    const float* A;
    const float* B;
    const float* bias;
    float* C;
};

__global__ __launch_bounds__(256) void gemm4(Job j0, Job j1, Job j2, Job j3)
{
    extern __shared__ float dsm[];
    float* Asm = dsm;                    // G4STG stages of A
    float* Bsm = dsm + G4STG * G4_AW;    // G4STG stages of B

    Job j = (blockIdx.z == 0) ? j0 : (blockIdx.z == 1) ? j1
          : (blockIdx.z == 2) ? j2 : j3;

    const int tid = threadIdx.x;
    const int wid = tid >> 5;
    const int lane = tid & 31;
    const int g = lane >> 2;
    const int tig = lane & 3;
    const int warp_m = wid >> 1;
    const int warp_n = wid & 1;

    const int m0 = blockIdx.y * 128;
    const int n0 = blockIdx.x * 64;

    const int ar = tid >> 1;
    const int ak = (tid & 1) << 3;
    const int br = tid >> 4;
    const int bc = (tid & 15) << 2;

    uint32_t as_s = (uint32_t)__cvta_generic_to_shared(Asm);
    uint32_t bs_s = (uint32_t)__cvta_generic_to_shared(Bsm);

    const int NT = Ddim >> 4;  // 32

    float acc[2][4][4];
#pragma unroll
    for (int i = 0; i < 2; i++)
#pragma unroll
        for (int jj = 0; jj < 4; jj++)
#pragma unroll
            for (int q = 0; q < 4; q++) acc[i][jj][q] = 0.f;

    auto issue = [&](int stage, int kt) {
        const int kg = kt << 4;
        const float* s0 = j.A + (long)(m0 + ar) * Ddim + kg + ak;
        uint32_t d0 = as_s + stage * G4_AB + (ar * LDA + ak) * 4;
        CP16(d0, s0);
        CP16(d0 + 16, s0 + 4);
        const float* sb = j.B + (long)(kg + br) * Ddim + n0 + bc;
        uint32_t db = bs_s + stage * G4_BB + (br * LDB + bc) * 4;
        CP16(db, sb);
    };

    issue(0, 0); CP_COMMIT();
    issue(1, 1); CP_COMMIT();
    issue(2, 2); CP_COMMIT();

    for (int t = 0; t < NT; t++) {
        const int st = t & (G4STG - 1);
        CP_WAIT2();
        __syncthreads();

        if (t + 3 < NT) issue((t + 3) & (G4STG - 1), t + 3);
        CP_COMMIT();

        const float* as = Asm + st * G4_AW;
        const float* bs = Bsm + st * G4_BW;
        const int mb = warp_m * 32;
        const int nb = warp_n * 32;
#pragma unroll
        for (int ks = 0; ks < 2; ks++) {
            const int k0 = ks << 3;
            uint32_t a[2][4], b[4][2];
#pragma unroll
            for (int im = 0; im < 2; im++) {
                const float* ap = as + (mb + im * 16 + g) * LDA;
                a[im][0] = raw_tf32(ap[k0 + tig]);
                a[im][1] = raw_tf32(ap[8 * LDA + k0 + tig]);
                a[im][2] = raw_tf32(ap[k0 + tig + 4]);
                a[im][3] = raw_tf32(ap[8 * LDA + k0 + tig + 4]);
            }
#pragma unroll
            for (int in = 0; in < 4; in++) {
                const int nc = nb + in * 8 + g;
                b[in][0] = raw_tf32(bs[(k0 + tig) * LDB + nc]);
                b[in][1] = raw_tf32(bs[(k0 + tig + 4) * LDB + nc]);
            }
#pragma unroll
            for (int im = 0; im < 2; im++)
#pragma unroll
                for (int in = 0; in < 4; in++)
                    mma_tf32(acc[im][in], a[im], b[in]);
        }
    }

    __syncthreads();
    const int mb = warp_m * 32;
    const int nb = warp_n * 32;
#pragma unroll
    for (int im = 0; im < 2; im++) {
#pragma unroll
        for (int in = 0; in < 4; in++) {
            const int row = m0 + mb + im * 16 + g;
            const int col = n0 + nb + in * 8 + tig * 2;
            float bx = 0.f, by = 0.f;
            if (j.bias) { bx = j.bias[col]; by = j.bias[col + 1]; }
            float2 o0 = make_float2(acc[im][in][0] + bx, acc[im][in][1] + by);
            float2 o1 = make_float2(acc[im][in][2] + bx, acc[im][in][3] + by);
            *(float2*)&j.C[(long)row * Ddim + col] = o0;
            *(float2*)&j.C[(long)(row + 8) * Ddim + col] = o1;
        }
    }
}

// ---------------------------------------------------------------------------
// gemm_fin: out[b] = attn[b] @ pre1[b] + pre2[b]  (256x512, K=256 per batch)
// 256 threads, 64x64 tile, 8 warps (2m x 4n), warp tile 32x16, 4 stages.
// ---------------------------------------------------------------------------
#define FSTG 4
#define F_AB (64 * LDA * 4)
#define F_BB (16 * LDB * 4)

__global__ __launch_bounds__(256) void gemm_fin(
    const float* __restrict__ attn, const float* __restrict__ pre1,
    const float* __restrict__ pre2, float* __restrict__ out)
{
    __shared__ float As[FSTG][64 * LDA];
    __shared__ float Bs[FSTG][16 * LDB];

    const int z = blockIdx.z;
    const float* A = attn + (long)z * Tdim * Sdim;
    const float* B = pre1 + (long)z * Sdim * Ddim;
    const float* addend = pre2 + (long)z * Tdim * Ddim;
    float* C = out + (long)z * Tdim * Ddim;

    const int tid = threadIdx.x;
    const int wid = tid >> 5;
    const int lane = tid & 31;
    const int g = lane >> 2;
    const int tig = lane & 3;
    const int warp_m = wid >> 2;
    const int warp_n = wid & 3;

    const int m0 = blockIdx.y * 64;
    const int n0 = blockIdx.x * 64;

    const int ar = tid >> 2;
    const int ak = (tid & 3) << 2;
    const int br = tid >> 4;
    const int bc = (tid & 15) << 2;

    uint32_t as_s = (uint32_t)__cvta_generic_to_shared(&As[0][0]);
    uint32_t bs_s = (uint32_t)__cvta_generic_to_shared(&Bs[0][0]);

    const int NT = Sdim >> 4;  // 16

    float acc[2][2][4];
#pragma unroll
    for (int i = 0; i < 2; i++)
#pragma unroll
        for (int jj = 0; jj < 2; jj++)
#pragma unroll
            for (int q = 0; q < 4; q++) acc[i][jj][q] = 0.f;

    auto issue = [&](int stage, int kt) {
        const int kg = kt << 4;
        const float* s0 = A + (long)(m0 + ar) * Sdim + kg + ak;
        uint32_t d0 = as_s + stage * F_AB + (ar * LDA + ak) * 4;
        CP16(d0, s0);
        const float* sb = B + (long)(kg + br) * Ddim + n0 + bc;
        uint32_t db = bs_s + stage * F_BB + (br * LDB + bc) * 4;
        CP16(db, sb);
    };

#pragma unroll
    for (int p = 0; p < FSTG - 1; p++) {
        if (p < NT) issue(p, p);
        CP_COMMIT();
    }

    for (int t = 0; t < NT; t++) {
        const int st = t & (FSTG - 1);
        CP_WAIT2();
        __syncthreads();

        if (t + FSTG - 1 < NT) issue((t + FSTG - 1) & (FSTG - 1), t + FSTG - 1);
        CP_COMMIT();

        const float* as = As[st];
        const float* bs = Bs[st];
        const int mb = warp_m * 32;
        const int nb = warp_n * 16;
#pragma unroll
        for (int ks = 0; ks < 2; ks++) {
            const int k0 = ks << 3;
            uint32_t a[2][4], b[2][2];
#pragma unroll
            for (int im = 0; im < 2; im++) {
                const float* ap = as + (mb + im * 16 + g) * LDA;
                a[im][0] = raw_tf32(ap[k0 + tig]);
                a[im][1] = raw_tf32(ap[8 * LDA + k0 + tig]);
                a[im][2] = raw_tf32(ap[k0 + tig + 4]);
                a[im][3] = raw_tf32(ap[8 * LDA + k0 + tig + 4]);
            }
#pragma unroll
            for (int in = 0; in < 2; in++) {
                const int nc = nb + in * 8 + g;
                b[in][0] = raw_tf32(bs[(k0 + tig) * LDB + nc]);
                b[in][1] = raw_tf32(bs[(k0 + tig + 4) * LDB + nc]);
            }
#pragma unroll
            for (int im = 0; im < 2; im++)
#pragma unroll
                for (int in = 0; in < 2; in++)
                    mma_tf32(acc[im][in], a[im], b[in]);
        }
    }

    __syncthreads();
    const int mb = warp_m * 32;
    const int nb = warp_n * 16;
#pragma unroll
    for (int im = 0; im < 2; im++) {
#pragma unroll
        for (int in = 0; in < 2; in++) {
            const int row = m0 + mb + im * 16 + g;
            const int col = n0 + nb + in * 8 + tig * 2;
            const float2 r0 = *(const float2*)&addend[(long)row * Ddim + col];
            const float2 r1 = *(const float2*)&addend[(long)(row + 8) * Ddim + col];
            float2 o0 = make_float2(acc[im][in][0] + r0.x, acc[im][in][1] + r0.y);
            float2 o1 = make_float2(acc[im][in][2] + r1.x, acc[im][in][3] + r1.y);
            *(float2*)&C[(long)row * Ddim + col] = o0;
            *(float2*)&C[(long)(row + 8) * Ddim + col] = o1;
        }
    }
}

// ---------------------------------------------------------------------------
// score[b,t,s] = sum_d v[d] * tanh(wq[b,t,d] + uh[b,s,d])
// ---------------------------------------------------------------------------
__global__ __launch_bounds__(256) void score_kernel(
    const float* __restrict__ wq, const float* __restrict__ uh,
    const float* __restrict__ v, float* __restrict__ sc)
{
    __shared__ float Aq[32][33];
    __shared__ float Au[32][33];
    __shared__ float vs[32];

    const int b = blockIdx.z;
    const int t0 = blockIdx.y * 32;
    const int s0 = blockIdx.x * 32;
    const int tid = threadIdx.x;
    const int tx = tid & 15, ty = tid >> 4;

    const float* wqb = wq + ((long)b * Tdim + t0) * Ddim;
    const float* uhb = uh + ((long)b * Sdim + s0) * Ddim;

    const int lr = tid >> 3;
    const int lc = (tid & 7) << 2;

    float acc00 = 0.f, acc01 = 0.f, acc10 = 0.f, acc11 = 0.f;

    for (int d0 = 0; d0 < Ddim; d0 += 32) {
        float4 q = *(const float4*)&wqb[(long)lr * Ddim + d0 + lc];
        Aq[lc + 0][lr] = q.x;
        Aq[lc + 1][lr] = q.y;
        Aq[lc + 2][lr] = q.z;
        Aq[lc + 3][lr] = q.w;
        float4 u = *(const float4*)&uhb[(long)lr * Ddim + d0 + lc];
        Au[lc + 0][lr] = u.x;
        Au[lc + 1][lr] = u.y;
        Au[lc + 2][lr] = u.z;
        Au[lc + 3][lr] = u.w;
        if (tid < 32) vs[tid] = v[d0 + tid];
        __syncthreads();

#pragma unroll
        for (int dk = 0; dk < 32; dk++) {
            float vv = vs[dk];
            float a0 = Aq[dk][ty * 2 + 0];
            float a1 = Aq[dk][ty * 2 + 1];
            float u0 = Au[dk][tx * 2 + 0];
            float u1 = Au[dk][tx * 2 + 1];
            acc00 += vv * tanh_fast(a0 + u0);
            acc01 += vv * tanh_fast(a0 + u1);
            acc10 += vv * tanh_fast(a1 + u0);
            acc11 += vv * tanh_fast(a1 + u1);
        }
        __syncthreads();
    }

    float* scp = sc + ((long)b * Tdim + t0) * Sdim + s0;
    scp[(long)(ty * 2 + 0) * Sdim + tx * 2 + 0] = acc00;
    scp[(long)(ty * 2 + 0) * Sdim + tx * 2 + 1] = acc01;
    scp[(long)(ty * 2 + 1) * Sdim + tx * 2 + 0] = acc10;
    scp[(long)(ty * 2 + 1) * Sdim + tx * 2 + 1] = acc11;
}

// ---------------------------------------------------------------------------
// Masked softmax: warp-per-row, 8 rows/block (reference semantics).
// ---------------------------------------------------------------------------
__global__ __launch_bounds__(256) void softmax_kernel(
    float* __restrict__ sc, const int* __restrict__ mask,
    float* __restrict__ attn_out)
{
    const int warp = threadIdx.x >> 5;
    const int lane = threadIdx.x & 31;
    const int row = blockIdx.x * 8 + warp;
    const int b = row >> 8;

    float* rp = sc + (long)row * Sdim;
    const int* mp = mask + b * Sdim;

    float x[8];
    float m = -1e30f;
#pragma unroll
    for (int i = 0; i < 8; i++) {
        x[i] = rp[i * 32 + lane];
        m = fmaxf(m, x[i]);
    }
#pragma unroll
    for (int o = 16; o > 0; o >>= 1)
        m = fmaxf(m, __shfl_xor_sync(0xffffffffu, m, o));

    float e[8];
    float sum = 0.f;
#pragma unroll
    for (int i = 0; i < 8; i++) {
        float keep = 1.0f - (float)mp[i * 32 + lane];
        e[i] = __expf(x[i] - m) * keep;
        sum += e[i];
    }
#pragma unroll
    for (int o = 16; o > 0; o >>= 1)
        sum += __shfl_xor_sync(0xffffffffu, sum, o);

    const float inv = 1.0f / sum;
    float* ap = attn_out ? attn_out + (long)row * Sdim : nullptr;
#pragma unroll
    for (int i = 0; i < 8; i++) {
        float a = e[i] * inv;
        rp[i * 32 + lane] = a;
        if (ap) ap[i * 32 + lane] = a;
    }
}

// ---------------------------------------------------------------------------
extern "C" void kernel_launch(void* const* d_in, const int* in_sizes, int n_in,
                              void* d_out, int out_size)
{
    const float* out_in = (const float*)d_in[0];  // (B,T,D)
    const float* ctx    = (const float*)d_in[1];  // (B,S,D)
    const int*   mask   = (const int*)d_in[2];    // (B,S)
    const float* Wq     = (const float*)d_in[3];  // (D,D)
    const float* bq     = (const float*)d_in[4];  // (D,)
    const float* Wc     = (const float*)d_in[5];  // (D,D)
    const float* v      = (const float*)d_in[6];  // (D,)
    const float* Wout   = (const float*)d_in[7];  // (2D,D)
    const float* bout   = (const float*)d_in[8];  // (D,)

    float *p_wq, *p_uh, *p_sc, *p_pre1, *p_pre2;
    cudaGetSymbolAddress((void**)&p_wq, g_wq);
    cudaGetSymbolAddress((void**)&p_uh, g_uh);
    cudaGetSymbolAddress((void**)&p_sc, g_sc);
    cudaGetSymbolAddress((void**)&p_pre1, g_pre1);
    cudaGetSymbolAddress((void**)&p_pre2, g_pre2);

    const long BTD = (long)Bdim * Tdim * Ddim;  // 524288
    const long BTS = (long)Bdim * Tdim * Sdim;  // 262144
    float* out_f = (float*)d_out;
    float* attn_out = ((long)out_size >= BTD + BTS) ? (out_f + BTD) : nullptr;

    // 1) Four fused 1024x512x512 GEMMs (4-stage dynamic-smem pipeline)
    static bool attr_set = false;
    if (!attr_set) {
        cudaFuncSetAttribute(gemm4,
                             cudaFuncAttributeMaxDynamicSharedMemorySize,
                             G4_DYN);
        attr_set = true;
    }
    Job j0{out_in, Wq, bq, p_wq};
    Job j1{ctx, Wc, nullptr, p_uh};
    Job j2{ctx, Wout, nullptr, p_pre1};
    Job j3{out_in, Wout + (long)Ddim * Ddim, bout, p_pre2};
    gemm4<<<dim3(Ddim / 64, (Bdim * Tdim) / 128, 4), 256, G4_DYN>>>(
        j0, j1, j2, j3);

    // 2) score
    score_kernel<<<dim3(Sdim / 32, Tdim / 32, Bdim), 256>>>(p_wq, p_uh, v, p_sc);

    // 3) masked softmax (attn in-place in g_sc, also to d_out attn region)
    softmax_kernel<<<(Bdim * Tdim) / 8, 256>>>(p_sc, mask, attn_out);

    // 4) out = attn @ pre1 + pre2   (batched 256x512, K=256)
    gemm_fin<<<dim3(Ddim / 64, Tdim / 64, Bdim), 256>>>(p_sc, p_pre1, p_pre2, out_f);
}